// round 3
// baseline (speedup 1.0000x reference)
#include <cuda_runtime.h>
#include <cuda_fp16.h>
#include <cstdint>

// Problem dims (fixed by reference)
#define DIN   4096
#define DOUT  4096
#define MTOT  8192
#define QG    128
#define NGRP  (DIN / QG)      // 32

// GEMM tiling (int8 path)
#define MT     128
#define NT     128
#define KB     64             // int8 k-elems per stage
#define NKIT   (DIN / KB)     // 64
#define STAGES 4
#define ROWB   80             // smem bytes per 64-byte row (64 data + 16 pad)
#define STG_BYTES ((MT + NT) * ROWB)        // 20480
#define SW_OFF  (STAGES * STG_BYTES)        // 81920 : s_w table [32 g][128 n] f32
#define SMEM_TOTAL (SW_OFF + NGRP * NT * 4) // 98304

// ------------------------- device scratch (no cudaMalloc allowed) ----------
__device__ int8_t g_xq[(size_t)MTOT * DIN];   // 32 MB: exact int8 activations
__device__ int8_t g_wq[(size_t)DOUT * DIN];   // 16 MB: exact int8 weights (q - z)
__device__ float  g_ws[(size_t)DOUT * NGRP];  // per (row, group) weight scale
__device__ float  g_sx[MTOT];                 // per-token activation scale
__device__ float  g_scale[DIN];               // clip(exp(log_scale))

// ------------------------- helpers -----------------------------------------
__device__ __forceinline__ uint32_t smem_u32(const void* p) {
    uint32_t a;
    asm("{ .reg .u64 t; cvta.to.shared.u64 t, %1; cvt.u32.u64 %0, t; }" : "=r"(a) : "l"(p));
    return a;
}
__device__ __forceinline__ void cp16(uint32_t dst, const void* src) {
    asm volatile("cp.async.cg.shared.global [%0], [%1], 16;" :: "r"(dst), "l"(src));
}
__device__ __forceinline__ void ldm4(uint32_t* r, uint32_t a) {
    asm volatile("ldmatrix.sync.aligned.m8n8.x4.shared.b16 {%0,%1,%2,%3}, [%4];"
                 : "=r"(r[0]), "=r"(r[1]), "=r"(r[2]), "=r"(r[3]) : "r"(a));
}
// s8 x s8 -> s32, m16n8k32
__device__ __forceinline__ void imma16832(int* c, const uint32_t* a, const uint32_t* b) {
    asm volatile(
        "mma.sync.aligned.m16n8k32.row.col.s32.s8.s8.s32 "
        "{%0,%1,%2,%3}, {%4,%5,%6,%7}, {%8,%9}, {%0,%1,%2,%3};"
        : "+r"(c[0]), "+r"(c[1]), "+r"(c[2]), "+r"(c[3])
        : "r"(a[0]), "r"(a[1]), "r"(a[2]), "r"(a[3]), "r"(b[0]), "r"(b[1]));
}

// ------------------------- kernel 1: scale ---------------------------------
__global__ void k_scale(const float* __restrict__ ls) {
    int i = blockIdx.x * blockDim.x + threadIdx.x;
    if (i < DIN) {
        float s = expf(ls[i]);
        g_scale[i] = fminf(fmaxf(s, 1e-4f), 1e4f);
    }
}

// ------------------------- kernel 2: weight fake-quant -> int8 + scale -----
// one warp per (row, group-of-128); 4 elems/thread
__global__ __launch_bounds__(256) void k_wq(const float* __restrict__ w) {
    int wid = threadIdx.x >> 5, lane = threadIdx.x & 31;
    int gid = blockIdx.x * 8 + wid;          // 0 .. DOUT*NGRP-1
    int row = gid >> 5;                      // / NGRP (NGRP==32)
    int grp = gid & 31;
    int k0  = grp * QG + lane * 4;

    float4 wv = *(const float4*)(w + (size_t)row * DIN + k0);
    float4 sc = *(const float4*)(g_scale + k0);
    float v0 = wv.x * sc.x, v1 = wv.y * sc.y, v2 = wv.z * sc.z, v3 = wv.w * sc.w;

    float mx = fmaxf(fmaxf(v0, v1), fmaxf(v2, v3));
    float mn = fminf(fminf(v0, v1), fminf(v2, v3));
    #pragma unroll
    for (int o = 16; o; o >>= 1) {
        mx = fmaxf(mx, __shfl_xor_sync(0xFFFFFFFFu, mx, o));
        mn = fminf(mn, __shfl_xor_sync(0xFFFFFFFFu, mn, o));
    }
    float s = fmaxf(mx - mn, 1e-5f) / 15.0f;
    float z = fminf(fmaxf(-rintf(mn / s), 0.0f), 15.0f);

    // integer part (q - z) in [-15, 15], exact
    float q0 = fminf(fmaxf(rintf(v0 / s) + z, 0.0f), 15.0f) - z;
    float q1 = fminf(fmaxf(rintf(v1 / s) + z, 0.0f), 15.0f) - z;
    float q2 = fminf(fmaxf(rintf(v2 / s) + z, 0.0f), 15.0f) - z;
    float q3 = fminf(fmaxf(rintf(v3 / s) + z, 0.0f), 15.0f) - z;

    char4 c4;
    c4.x = (char)__float2int_rn(q0);
    c4.y = (char)__float2int_rn(q1);
    c4.z = (char)__float2int_rn(q2);
    c4.w = (char)__float2int_rn(q3);
    *(char4*)(g_wq + (size_t)row * DIN + k0) = c4;
    if (lane == 0) g_ws[(size_t)row * NGRP + grp] = s;
}

// ------------------------- kernel 3: activation fake-quant -> int8 ---------
__global__ __launch_bounds__(256) void k_aq(const float* __restrict__ x) {
    int t = blockIdx.x, tid = threadIdx.x;
    int wid = tid >> 5, lane = tid & 31;
    __shared__ float red[8];

    float v[16];
    float m = 0.0f;
    #pragma unroll
    for (int i = 0; i < 4; i++) {
        int k = (i * 256 + tid) * 4;
        float4 xv = *(const float4*)(x + (size_t)t * DIN + k);
        float4 sc = *(const float4*)(g_scale + k);
        v[i * 4 + 0] = xv.x / sc.x;
        v[i * 4 + 1] = xv.y / sc.y;
        v[i * 4 + 2] = xv.z / sc.z;
        v[i * 4 + 3] = xv.w / sc.w;
        m = fmaxf(m, fmaxf(fmaxf(fabsf(v[i*4+0]), fabsf(v[i*4+1])),
                           fmaxf(fabsf(v[i*4+2]), fabsf(v[i*4+3]))));
    }
    #pragma unroll
    for (int o = 16; o; o >>= 1) m = fmaxf(m, __shfl_xor_sync(0xFFFFFFFFu, m, o));
    if (lane == 0) red[wid] = m;
    __syncthreads();
    if (wid == 0) {
        float tmx = red[lane & 7];
        #pragma unroll
        for (int o = 4; o; o >>= 1) tmx = fmaxf(tmx, __shfl_xor_sync(0xFFFFFFFFu, tmx, o));
        if (lane == 0) red[0] = tmx;
    }
    __syncthreads();
    float s = fmaxf(red[0], 1e-5f) / 127.0f;
    if (tid == 0) g_sx[t] = s;

    #pragma unroll
    for (int i = 0; i < 4; i++) {
        int k = (i * 256 + tid) * 4;
        char4 c4;
        c4.x = (char)__float2int_rn(fminf(fmaxf(rintf(v[i*4+0] / s), -128.0f), 127.0f));
        c4.y = (char)__float2int_rn(fminf(fmaxf(rintf(v[i*4+1] / s), -128.0f), 127.0f));
        c4.z = (char)__float2int_rn(fminf(fmaxf(rintf(v[i*4+2] / s), -128.0f), 127.0f));
        c4.w = (char)__float2int_rn(fminf(fmaxf(rintf(v[i*4+3] / s), -128.0f), 127.0f));
        *(char4*)(g_xq + (size_t)t * DIN + k) = c4;
    }
}

// ------------------------- kernel 4: int8 GEMM (imma + cp.async) -----------
__device__ __forceinline__ void issue_stage(uint32_t sb, int m0, int n0, int kb,
                                            int s, int tid) {
    uint32_t sA = sb + s * STG_BYTES;
    uint32_t sB = sA + MT * ROWB;
    // A: 128 rows x 64 B  (512 cp16, 2/thread)
    #pragma unroll
    for (int j = 0; j < 2; j++) {
        int seg = tid + j * 256;
        int r = seg >> 2, c = seg & 3;
        cp16(sA + r * ROWB + c * 16, g_xq + (size_t)(m0 + r) * DIN + kb * KB + c * 16);
    }
    // B: 128 rows x 64 B
    #pragma unroll
    for (int j = 0; j < 2; j++) {
        int seg = tid + j * 256;
        int r = seg >> 2, c = seg & 3;
        cp16(sB + r * ROWB + c * 16, g_wq + (size_t)(n0 + r) * DIN + kb * KB + c * 16);
    }
    asm volatile("cp.async.commit_group;" ::: "memory");
}

__global__ __launch_bounds__(256, 1) void k_gemm(const float* __restrict__ bias,
                                                 float* __restrict__ out) {
    extern __shared__ char smem[];
    const uint32_t sb = smem_u32(smem);
    float* sws = (float*)(smem + SW_OFF);     // [NGRP][NT]
    int tid = threadIdx.x, lane = tid & 31, wid = tid >> 5;
    int wm = wid & 1, wn = wid >> 1;          // warp grid 2(m) x 4(n)
    int bid = blockIdx.x;
    int nt = bid & 31, mt = bid >> 5;
    int m0 = mt * MT, n0 = nt * NT;
    int qr = lane >> 2, qc = lane & 3;

    // fill per-(group, col) weight-scale table
    #pragma unroll
    for (int j = 0; j < 16; j++) {
        int t = tid + j * 256;                // 4096 entries
        int g = t >> 7, n = t & 127;
        sws[g * NT + n] = g_ws[(size_t)(n0 + n) * NGRP + g];
    }

    // prologue: stages 0..2
    issue_stage(sb, m0, n0, 0, 0, tid);
    issue_stage(sb, m0, n0, 1, 1, tid);
    issue_stage(sb, m0, n0, 2, 2, tid);

    int   ci[4][4][4];
    float cf[4][4][4];
    #pragma unroll
    for (int i = 0; i < 4; i++)
        #pragma unroll
        for (int j = 0; j < 4; j++)
            #pragma unroll
            for (int k = 0; k < 4; k++) { ci[i][j][k] = 0; cf[i][j][k] = 0.0f; }

    for (int kb = 0; kb < NKIT; kb++) {
        int s = kb & 3;
        asm volatile("cp.async.wait_group 2;" ::: "memory");
        __syncthreads();

        if (kb + 3 < NKIT) issue_stage(sb, m0, n0, kb + 3, (kb + 3) & 3, tid);
        else               asm volatile("cp.async.commit_group;" ::: "memory");

        uint32_t sA = sb + s * STG_BYTES;
        uint32_t sB = sA + MT * ROWB;

        #pragma unroll
        for (int ks = 0; ks < 2; ks++) {
            uint32_t a[4][4], b[4][2];
            #pragma unroll
            for (int mi = 0; mi < 4; mi++) {
                uint32_t addr = sA + (uint32_t)(wm * 64 + mi * 16 + (lane & 15)) * ROWB
                              + ks * 32 + ((lane >> 4) << 4);
                ldm4(a[mi], addr);
            }
            #pragma unroll
            for (int nj = 0; nj < 2; nj++) {
                uint32_t r[4];
                int g = lane >> 3;
                uint32_t addr = sB + (uint32_t)(wn * 32 + nj * 16 + ((g >> 1) << 3) + (lane & 7)) * ROWB
                              + ks * 32 + ((g & 1) << 4);
                ldm4(r, addr);
                b[nj * 2][0] = r[0]; b[nj * 2][1] = r[1];
                b[nj * 2 + 1][0] = r[2]; b[nj * 2 + 1][1] = r[3];
            }
            #pragma unroll
            for (int mi = 0; mi < 4; mi++)
                #pragma unroll
                for (int ni = 0; ni < 4; ni++)
                    imma16832(ci[mi][ni], a[mi], b[ni]);
        }

        // group boundary: fold per-(n, group) weight scale, reset int acc
        if (kb & 1) {
            int g = kb >> 1;
            #pragma unroll
            for (int ni = 0; ni < 4; ni++) {
                float2 sw = *(const float2*)(sws + g * NT + wn * 32 + ni * 8 + 2 * qc);
                #pragma unroll
                for (int mi = 0; mi < 4; mi++) {
                    cf[mi][ni][0] += sw.x * (float)ci[mi][ni][0];
                    cf[mi][ni][1] += sw.y * (float)ci[mi][ni][1];
                    cf[mi][ni][2] += sw.x * (float)ci[mi][ni][2];
                    cf[mi][ni][3] += sw.y * (float)ci[mi][ni][3];
                    ci[mi][ni][0] = 0; ci[mi][ni][1] = 0;
                    ci[mi][ni][2] = 0; ci[mi][ni][3] = 0;
                }
            }
        }
    }

    // ---------------- epilogue: out = cf * s_x[m] + bias[n] ----------------
    #pragma unroll
    for (int mi = 0; mi < 4; mi++) {
        int row0 = m0 + wm * 64 + mi * 16 + qr;
        float sx0 = g_sx[row0], sx1 = g_sx[row0 + 8];
        #pragma unroll
        for (int ni = 0; ni < 4; ni++) {
            int col = n0 + wn * 32 + ni * 8 + 2 * qc;
            float2 bv = *(const float2*)(bias + col);
            float2 o0, o1;
            o0.x = cf[mi][ni][0] * sx0 + bv.x;
            o0.y = cf[mi][ni][1] * sx0 + bv.y;
            o1.x = cf[mi][ni][2] * sx1 + bv.x;
            o1.y = cf[mi][ni][3] * sx1 + bv.y;
            *(float2*)(out + (size_t)row0 * DOUT + col) = o0;
            *(float2*)(out + (size_t)(row0 + 8) * DOUT + col) = o1;
        }
    }
}

// ------------------------- launch ------------------------------------------
extern "C" void kernel_launch(void* const* d_in, const int* in_sizes, int n_in,
                              void* d_out, int out_size) {
    (void)in_sizes; (void)n_in; (void)out_size;
    const float* x    = (const float*)d_in[0];
    const float* w    = (const float*)d_in[1];
    const float* bias = (const float*)d_in[2];
    const float* ls   = (const float*)d_in[3];
    float* out = (float*)d_out;

    k_scale<<<16, 256>>>(ls);
    k_wq<<<(DOUT * NGRP) / 8, 256>>>(w);
    k_aq<<<MTOT, 256>>>(x);

    cudaFuncSetAttribute(k_gemm, cudaFuncAttributeMaxDynamicSharedMemorySize, SMEM_TOTAL);
    k_gemm<<<(MTOT / MT) * (DOUT / NT), 256, SMEM_TOTAL>>>(bias, out);
}

// round 4
// speedup vs baseline: 2.8402x; 2.8402x over previous
#include <cuda_runtime.h>
#include <cuda_fp16.h>
#include <cstdint>

// Problem dims (fixed by reference)
#define DIN   4096
#define DOUT  4096
#define MTOT  8192
#define QG    128
#define NGRP  (DIN / QG)

// GEMM tiling
#define MT     128
#define NT     128
#define KB     64             // fp16 k-elems per stage (4 mma k-steps)
#define NKIT   (DIN / KB)     // 64
#define STAGES 3
#define ROWB   144            // smem bytes per 64-half row (128 data + 16 pad, odd multiple of 16)
#define STG_BYTES ((MT + NT) * ROWB)        // 36864
#define SMEM_TOTAL (STAGES * STG_BYTES)     // 110592

// ------------------------- device scratch (no cudaMalloc allowed) ----------
__device__ __half g_xq[(size_t)MTOT * DIN];   // quantized activations (exact ints in fp16)
__device__ __half g_wq[(size_t)DOUT * DIN];   // dequantized weights in fp16
__device__ float  g_sx[MTOT];                 // per-token activation scale
__device__ float  g_scale[DIN];               // clip(exp(log_scale))

// ------------------------- helpers -----------------------------------------
__device__ __forceinline__ uint32_t smem_u32(const void* p) {
    uint32_t a;
    asm("{ .reg .u64 t; cvta.to.shared.u64 t, %1; cvt.u32.u64 %0, t; }" : "=r"(a) : "l"(p));
    return a;
}
__device__ __forceinline__ void cp16(uint32_t dst, const void* src) {
    asm volatile("cp.async.cg.shared.global [%0], [%1], 16;" :: "r"(dst), "l"(src));
}
__device__ __forceinline__ void ldm4(uint32_t* r, uint32_t a) {
    asm volatile("ldmatrix.sync.aligned.m8n8.x4.shared.b16 {%0,%1,%2,%3}, [%4];"
                 : "=r"(r[0]), "=r"(r[1]), "=r"(r[2]), "=r"(r[3]) : "r"(a));
}
__device__ __forceinline__ void mma16816(float* c, const uint32_t* a, const uint32_t* b) {
    asm volatile(
        "mma.sync.aligned.m16n8k16.row.col.f32.f16.f16.f32 "
        "{%0,%1,%2,%3}, {%4,%5,%6,%7}, {%8,%9}, {%0,%1,%2,%3};"
        : "+f"(c[0]), "+f"(c[1]), "+f"(c[2]), "+f"(c[3])
        : "r"(a[0]), "r"(a[1]), "r"(a[2]), "r"(a[3]), "r"(b[0]), "r"(b[1]));
}

// ------------------------- kernel 1: scale ---------------------------------
__global__ void k_scale(const float* __restrict__ ls) {
    int i = blockIdx.x * blockDim.x + threadIdx.x;
    if (i < DIN) {
        float s = expf(ls[i]);
        g_scale[i] = fminf(fmaxf(s, 1e-4f), 1e4f);
    }
}

// ------------------------- kernel 2: weight fake-quant -> fp16 -------------
// one warp per (row, group-of-128); 4 elems/thread
__global__ __launch_bounds__(256) void k_wq(const float* __restrict__ w) {
    int wid = threadIdx.x >> 5, lane = threadIdx.x & 31;
    int gid = blockIdx.x * 8 + wid;          // 0 .. DOUT*NGRP-1
    int row = gid >> 5;                      // / NGRP (NGRP==32)
    int grp = gid & 31;
    int k0  = grp * QG + lane * 4;

    float4 wv = *(const float4*)(w + (size_t)row * DIN + k0);
    float4 sc = *(const float4*)(g_scale + k0);
    float v0 = wv.x * sc.x, v1 = wv.y * sc.y, v2 = wv.z * sc.z, v3 = wv.w * sc.w;

    float mx = fmaxf(fmaxf(v0, v1), fmaxf(v2, v3));
    float mn = fminf(fminf(v0, v1), fminf(v2, v3));
    #pragma unroll
    for (int o = 16; o; o >>= 1) {
        mx = fmaxf(mx, __shfl_xor_sync(0xFFFFFFFFu, mx, o));
        mn = fminf(mn, __shfl_xor_sync(0xFFFFFFFFu, mn, o));
    }
    float s = fmaxf(mx - mn, 1e-5f) / 15.0f;
    float z = fminf(fmaxf(-rintf(mn / s), 0.0f), 15.0f);

    float q0 = (fminf(fmaxf(rintf(v0 / s) + z, 0.0f), 15.0f) - z) * s;
    float q1 = (fminf(fmaxf(rintf(v1 / s) + z, 0.0f), 15.0f) - z) * s;
    float q2 = (fminf(fmaxf(rintf(v2 / s) + z, 0.0f), 15.0f) - z) * s;
    float q3 = (fminf(fmaxf(rintf(v3 / s) + z, 0.0f), 15.0f) - z) * s;

    __half2* dst = (__half2*)(g_wq + (size_t)row * DIN + k0);
    dst[0] = __halves2half2(__float2half_rn(q0), __float2half_rn(q1));
    dst[1] = __halves2half2(__float2half_rn(q2), __float2half_rn(q3));
}

// ------------------------- kernel 3: activation fake-quant -----------------
// one block (256 thr) per token row; store exact integers (fp16) + row scale
__global__ __launch_bounds__(256) void k_aq(const float* __restrict__ x) {
    int t = blockIdx.x, tid = threadIdx.x;
    int wid = tid >> 5, lane = tid & 31;
    __shared__ float red[8];

    float v[16];
    float m = 0.0f;
    #pragma unroll
    for (int i = 0; i < 4; i++) {
        int k = (i * 256 + tid) * 4;
        float4 xv = *(const float4*)(x + (size_t)t * DIN + k);
        float4 sc = *(const float4*)(g_scale + k);
        v[i * 4 + 0] = xv.x / sc.x;
        v[i * 4 + 1] = xv.y / sc.y;
        v[i * 4 + 2] = xv.z / sc.z;
        v[i * 4 + 3] = xv.w / sc.w;
        m = fmaxf(m, fmaxf(fmaxf(fabsf(v[i*4+0]), fabsf(v[i*4+1])),
                           fmaxf(fabsf(v[i*4+2]), fabsf(v[i*4+3]))));
    }
    #pragma unroll
    for (int o = 16; o; o >>= 1) m = fmaxf(m, __shfl_xor_sync(0xFFFFFFFFu, m, o));
    if (lane == 0) red[wid] = m;
    __syncthreads();
    if (wid == 0) {
        float tmx = red[lane & 7];
        #pragma unroll
        for (int o = 4; o; o >>= 1) tmx = fmaxf(tmx, __shfl_xor_sync(0xFFFFFFFFu, tmx, o));
        if (lane == 0) red[0] = tmx;
    }
    __syncthreads();
    float s = fmaxf(red[0], 1e-5f) / 127.0f;
    if (tid == 0) g_sx[t] = s;

    #pragma unroll
    for (int i = 0; i < 4; i++) {
        int k = (i * 256 + tid) * 4;
        float q0 = fminf(fmaxf(rintf(v[i*4+0] / s), -128.0f), 127.0f);
        float q1 = fminf(fmaxf(rintf(v[i*4+1] / s), -128.0f), 127.0f);
        float q2 = fminf(fmaxf(rintf(v[i*4+2] / s), -128.0f), 127.0f);
        float q3 = fminf(fmaxf(rintf(v[i*4+3] / s), -128.0f), 127.0f);
        __half2* dst = (__half2*)(g_xq + (size_t)t * DIN + k);
        dst[0] = __halves2half2(__float2half_rn(q0), __float2half_rn(q1));
        dst[1] = __halves2half2(__float2half_rn(q2), __float2half_rn(q3));
    }
}

// ------------------------- kernel 4: GEMM (mma.sync + cp.async) ------------
// per stage: A 128 rows x 128B, B 128 rows x 128B; 8 chunks of 16B per row
__device__ __forceinline__ void issue_stage(uint32_t sb, int m0, int n0, int kb,
                                            int s, int tid) {
    uint32_t sA = sb + s * STG_BYTES;
    uint32_t sB = sA + MT * ROWB;
    #pragma unroll
    for (int j = 0; j < 4; j++) {          // A: 1024 cp16
        int seg = tid + j * 256;
        int r = seg >> 3, c = seg & 7;
        cp16(sA + r * ROWB + c * 16, g_xq + (size_t)(m0 + r) * DIN + kb * KB + c * 8);
    }
    #pragma unroll
    for (int j = 0; j < 4; j++) {          // B: 1024 cp16
        int seg = tid + j * 256;
        int r = seg >> 3, c = seg & 7;
        cp16(sB + r * ROWB + c * 16, g_wq + (size_t)(n0 + r) * DIN + kb * KB + c * 8);
    }
    asm volatile("cp.async.commit_group;" ::: "memory");
}

__global__ __launch_bounds__(256, 2) void k_gemm(const float* __restrict__ bias,
                                                 float* __restrict__ out) {
    extern __shared__ char smem[];
    const uint32_t sb = smem_u32(smem);
    int tid = threadIdx.x, lane = tid & 31, wid = tid >> 5;
    int wm = wid & 1, wn = wid >> 1;          // warp grid 2(m) x 4(n)
    int bid = blockIdx.x;
    int nt = bid & 31, mt = bid >> 5;
    int m0 = mt * MT, n0 = nt * NT;

    // prologue: stages 0,1
    issue_stage(sb, m0, n0, 0, 0, tid);
    issue_stage(sb, m0, n0, 1, 1, tid);

    float c[4][4][4];
    #pragma unroll
    for (int i = 0; i < 4; i++)
        #pragma unroll
        for (int j = 0; j < 4; j++)
            #pragma unroll
            for (int k = 0; k < 4; k++) c[i][j][k] = 0.0f;

    int s = 0;
    for (int kb = 0; kb < NKIT; kb++) {
        asm volatile("cp.async.wait_group 1;" ::: "memory");
        __syncthreads();

        if (kb + 2 < NKIT) issue_stage(sb, m0, n0, kb + 2, (s + 2 >= STAGES) ? s - 1 : s + 2, tid);
        else               asm volatile("cp.async.commit_group;" ::: "memory");

        uint32_t sA = sb + s * STG_BYTES;
        uint32_t sB = sA + MT * ROWB;

        #pragma unroll
        for (int ks = 0; ks < 4; ks++) {
            uint32_t a[4][4], b[4][2];
            #pragma unroll
            for (int mi = 0; mi < 4; mi++) {
                uint32_t addr = sA + (uint32_t)(wm * 64 + mi * 16 + (lane & 15)) * ROWB
                              + ks * 32 + ((lane >> 4) << 4);
                ldm4(a[mi], addr);
            }
            #pragma unroll
            for (int nj = 0; nj < 2; nj++) {
                uint32_t r[4];
                int g = lane >> 3;
                uint32_t addr = sB + (uint32_t)(wn * 32 + nj * 16 + ((g >> 1) << 3) + (lane & 7)) * ROWB
                              + ks * 32 + ((g & 1) << 4);
                ldm4(r, addr);
                b[nj * 2][0] = r[0]; b[nj * 2][1] = r[1];
                b[nj * 2 + 1][0] = r[2]; b[nj * 2 + 1][1] = r[3];
            }
            #pragma unroll
            for (int mi = 0; mi < 4; mi++)
                #pragma unroll
                for (int ni = 0; ni < 4; ni++)
                    mma16816(c[mi][ni], a[mi], b[ni]);
        }
        s = (s + 1 == STAGES) ? 0 : s + 1;
    }

    // ---------------- epilogue: out = D * s_x[m] + bias[n] -----------------
    int qr = lane >> 2, qc = lane & 3;
    #pragma unroll
    for (int mi = 0; mi < 4; mi++) {
        int row0 = m0 + wm * 64 + mi * 16 + qr;
        float sx0 = g_sx[row0], sx1 = g_sx[row0 + 8];
        #pragma unroll
        for (int ni = 0; ni < 4; ni++) {
            int col = n0 + wn * 32 + ni * 8 + 2 * qc;
            float2 bv = *(const float2*)(bias + col);
            float2 o0, o1;
            o0.x = c[mi][ni][0] * sx0 + bv.x;
            o0.y = c[mi][ni][1] * sx0 + bv.y;
            o1.x = c[mi][ni][2] * sx1 + bv.x;
            o1.y = c[mi][ni][3] * sx1 + bv.y;
            *(float2*)(out + (size_t)row0 * DOUT + col) = o0;
            *(float2*)(out + (size_t)(row0 + 8) * DOUT + col) = o1;
        }
    }
}

// ------------------------- launch ------------------------------------------
extern "C" void kernel_launch(void* const* d_in, const int* in_sizes, int n_in,
                              void* d_out, int out_size) {
    (void)in_sizes; (void)n_in; (void)out_size;
    const float* x    = (const float*)d_in[0];
    const float* w    = (const float*)d_in[1];
    const float* bias = (const float*)d_in[2];
    const float* ls   = (const float*)d_in[3];
    float* out = (float*)d_out;

    k_scale<<<16, 256>>>(ls);
    k_wq<<<(DOUT * NGRP) / 8, 256>>>(w);
    k_aq<<<MTOT, 256>>>(x);

    cudaFuncSetAttribute(k_gemm, cudaFuncAttributeMaxDynamicSharedMemorySize, SMEM_TOTAL);
    k_gemm<<<(MTOT / MT) * (DOUT / NT), 256, SMEM_TOTAL>>>(bias, out);
}